// round 14
// baseline (speedup 1.0000x reference)
#include <cuda_runtime.h>
#include <cuda_bf16.h>
#include <cstdint>

// ---------------------------------------------------------------------------
// Problem constants
//   V=400000, E=300, H=100, NH=200, N_EDUS=256, T=32, N_ACT=2
// Pipeline:
//   GEMM (emb-gather fused, double-buffered) -> xproj[8192,800]
//   lstm_rec (multi-acc + x-prefetch)        -> hA / hB
//   enc = masked mean                        -> enc[256,200]
//   parser: SINGLE CTA, Wt register-resident (thread t holds row t),
//           speculative matvec concurrent with decision. No cluster.
// ---------------------------------------------------------------------------

#define NSEQ 256
#define TT   32
#define MTOT (NSEQ*TT)   // 8192
#define GNN  800         // 2 dirs * 400 gates

__device__ float g_xproj[MTOT * GNN];   // 26.2 MB
__device__ float g_hA[MTOT * 200];      // 6.55 MB
__device__ float g_hB[MTOT * 200];      // 6.55 MB
__device__ float g_enc[NSEQ * 200];     // 0.2 MB

__device__ __forceinline__ float sigm(float x)   { return 1.0f / (1.0f + __expf(-x)); }
__device__ __forceinline__ float tanh_f(float x) { return 2.0f / (1.0f + __expf(-2.0f * x)) - 1.0f; }

// Dummy launch so ncu (-s 5 -c 1) lands on sgemm_tn next capture.
__global__ void prof_pad_kernel() {}

// ---------------------------------------------------------------------------
// SGEMM: g_xproj[m][n] = sum_k A[m][k] * W[n][k]   (identical to R10 pass)
// ---------------------------------------------------------------------------
__global__ __launch_bounds__(256, 2) void sgemm_tn(
    int asel, const float* __restrict__ W, int K,
    const int* __restrict__ tokens, const float* __restrict__ emb)
{
    const int N = GNN;
    const int tid  = threadIdx.x;
    const int tx   = tid & 15;
    const int ty   = tid >> 4;
    const int lrow = tid >> 1;          // 0..127
    const int lk   = (tid & 1) << 2;    // 0 or 4
    const int bm   = blockIdx.x * 128;
    const int bn   = blockIdx.y * 128;

    const float* Arow;
    {
        const int m = bm + lrow;
        if (asel == 0)      Arow = emb + (size_t)tokens[m] * K;
        else if (asel == 1) Arow = g_hA + (size_t)m * K;
        else                Arow = g_hB + (size_t)m * K;
    }
    const int  nrow   = bn + lrow;
    const bool wvalid = (nrow < N);
    const float* Wrow = W + (size_t)(wvalid ? nrow : 0) * K;

    __shared__ float As[2][8][128];
    __shared__ float Bs[2][8][128];

    float acc[8][8];
#pragma unroll
    for (int i = 0; i < 8; i++)
#pragma unroll
        for (int j = 0; j < 8; j++) acc[i][j] = 0.0f;

    {
        const int ka = lk;
        float4 av = make_float4(0.f, 0.f, 0.f, 0.f);
        float4 bv = make_float4(0.f, 0.f, 0.f, 0.f);
        if (ka < K)            av = *(const float4*)(Arow + ka);
        if (wvalid && ka < K)  bv = *(const float4*)(Wrow + ka);
        As[0][lk + 0][lrow] = av.x; As[0][lk + 1][lrow] = av.y;
        As[0][lk + 2][lrow] = av.z; As[0][lk + 3][lrow] = av.w;
        Bs[0][lk + 0][lrow] = bv.x; Bs[0][lk + 1][lrow] = bv.y;
        Bs[0][lk + 2][lrow] = bv.z; Bs[0][lk + 3][lrow] = bv.w;
    }
    __syncthreads();

    int buf = 0;
    for (int k0 = 0; k0 < K; k0 += 8) {
        float4 av2 = make_float4(0.f, 0.f, 0.f, 0.f);
        float4 bv2 = make_float4(0.f, 0.f, 0.f, 0.f);
        const bool more = (k0 + 8 < K);
        if (more) {
            const int kn = k0 + 8 + lk;
            if (kn < K)            av2 = *(const float4*)(Arow + kn);
            if (wvalid && kn < K)  bv2 = *(const float4*)(Wrow + kn);
        }

#pragma unroll
        for (int kk = 0; kk < 8; kk++) {
            float a[8], b[8];
            *(float4*)&a[0] = *(const float4*)&As[buf][kk][ty * 8];
            *(float4*)&a[4] = *(const float4*)&As[buf][kk][ty * 8 + 4];
            *(float4*)&b[0] = *(const float4*)&Bs[buf][kk][tx * 8];
            *(float4*)&b[4] = *(const float4*)&Bs[buf][kk][tx * 8 + 4];
#pragma unroll
            for (int i = 0; i < 8; i++)
#pragma unroll
                for (int j = 0; j < 8; j++) acc[i][j] += a[i] * b[j];
        }

        if (more) {
            const int nb = buf ^ 1;
            As[nb][lk + 0][lrow] = av2.x; As[nb][lk + 1][lrow] = av2.y;
            As[nb][lk + 2][lrow] = av2.z; As[nb][lk + 3][lrow] = av2.w;
            Bs[nb][lk + 0][lrow] = bv2.x; Bs[nb][lk + 1][lrow] = bv2.y;
            Bs[nb][lk + 2][lrow] = bv2.z; Bs[nb][lk + 3][lrow] = bv2.w;
        }
        __syncthreads();
        buf ^= 1;
    }

#pragma unroll
    for (int i = 0; i < 8; i++) {
        const int m = bm + ty * 8 + i;
        float* crow = g_xproj + (size_t)m * N;
#pragma unroll
        for (int j = 0; j < 8; j++) {
            const int n = bn + tx * 8 + j;
            if (n < N) crow[n] = acc[i][j];
        }
    }
}

// ---------------------------------------------------------------------------
// LSTM recurrence (identical to R10 pass)
// ---------------------------------------------------------------------------
__global__ __launch_bounds__(416, 1) void lstm_rec(
    const float* __restrict__ Whh, const float* __restrict__ bias,
    const int* __restrict__ lengths, int osel)
{
    const int b = blockIdx.x >> 1;
    const int d = blockIdx.x & 1;
    const int g = threadIdx.x;

    float* out = osel ? g_hB : g_hA;

    __shared__ __align__(16) float h_s[100];
    __shared__ float gates_s[400];

    float wreg[100];
    float bias_r = 0.0f;
    const float* xcol = g_xproj + (size_t)b * 32 * 800 + d * 400 + g;
    if (g < 400) {
        const float* wp = Whh + (size_t)(d * 400 + g) * 100;
#pragma unroll
        for (int k = 0; k < 100; k += 4) {
            float4 w = *(const float4*)(wp + k);
            wreg[k] = w.x; wreg[k + 1] = w.y; wreg[k + 2] = w.z; wreg[k + 3] = w.w;
        }
        bias_r = bias[d * 400 + g];
    }
    if (g < 100) h_s[g] = 0.0f;
    float c_r = 0.0f;
    const int len = lengths[b];

    float xv = 0.0f;
    if (g < 400) xv = xcol[(size_t)(d ? 31 : 0) * 800];
    __syncthreads();

    for (int s = 0; s < 32; s++) {
        const int t = d ? (31 - s) : s;
        float xn = 0.0f;
        if (s < 31 && g < 400) {
            const int tn = d ? (30 - s) : (s + 1);
            xn = xcol[(size_t)tn * 800];
        }
        if (g < 400) {
            float a0 = 0.f, a1 = 0.f, a2 = 0.f, a3 = 0.f;
#pragma unroll
            for (int k = 0; k < 100; k += 4) {
                float4 hv = *(const float4*)(h_s + k);
                a0 += wreg[k]     * hv.x;
                a1 += wreg[k + 1] * hv.y;
                a2 += wreg[k + 2] * hv.z;
                a3 += wreg[k + 3] * hv.w;
            }
            gates_s[g] = (xv + bias_r) + ((a0 + a1) + (a2 + a3));
        }
        __syncthreads();
        if (g < 100) {
            const bool valid = (t < len);
            const float iv = gates_s[g];
            const float fv = gates_s[100 + g];
            const float gv = gates_s[200 + g];
            const float ov = gates_s[300 + g];
            const float cn = sigm(fv) * c_r + sigm(iv) * tanh_f(gv);
            const float hn = sigm(ov) * tanh_f(cn);
            const float ho = valid ? hn : h_s[g];
            c_r = valid ? cn : c_r;
            out[(size_t)(b * 32 + t) * 200 + d * 100 + g] = valid ? hn : 0.0f;
            h_s[g] = ho;
        }
        xv = xn;
        __syncthreads();
    }
}

// ---------------------------------------------------------------------------
// enc[b][g] = (sum_t hA[b][t][g]) / len[b]
// ---------------------------------------------------------------------------
__global__ void enc_kernel(const int* __restrict__ lengths)
{
    const int b = blockIdx.x;
    const int g = threadIdx.x;
    if (g < 200) {
        float s = 0.0f;
#pragma unroll
        for (int t = 0; t < 32; t++) s += g_hA[(size_t)(b * 32 + t) * 200 + g];
        g_enc[b * 200 + g] = s / (float)lengths[b];
    }
}

// ---------------------------------------------------------------------------
// Single-CTA parser, Wt register-resident.
//   Thread t < 500 holds Wt row t (200 floats) in registers.
//   Per step: gather feat (+u) | sync | scores (warp 0, writes dec) +
//   speculative matvec (all t<500) | sync | apply action | sync.
//   Only __syncthreads — no cross-CTA anything, nothing can deadlock.
// ---------------------------------------------------------------------------
#define NSTEP     (2*NSEQ - 1)
#define OFF_STACK 0          // 256*200 = 51200
#define OFF_FEAT  51200      // 600
#define OFF_GAT   51800      // 512 (500 used)
#define OFF_WA    52312      // 1200
#define OFF_MISS  53512      // 200
#define OFF_U     53712      // 204 used 200 (53712*4 % 16 == 0)
#define PAR_SMEM_FLOATS 53916   // 215,664 B

__global__ __launch_bounds__(512, 1) void parser_kernel(
    const float* __restrict__ missing,
    const float* __restrict__ Wa, const float* __restrict__ ba,
    const float* __restrict__ Wt, const float* __restrict__ bt,
    float* __restrict__ out)
{
    extern __shared__ float sm[];
    const int t = threadIdx.x;

    float* stack = sm + OFF_STACK;
    float* feat  = sm + OFF_FEAT;
    float* gat   = sm + OFF_GAT;
    float* wa_s  = sm + OFF_WA;
    float* mis_s = sm + OFF_MISS;
    float* u_s   = sm + OFF_U;

    __shared__ float ba_s[2];
    __shared__ int   dec_s;

    // ---- init: Wa / missing to smem; Wt row t + bt[t] to registers ----
    for (int i = t; i < 1200; i += 512) wa_s[i]  = Wa[i];
    for (int i = t; i < 200;  i += 512) mis_s[i] = missing[i];
    if (t < 2) ba_s[t] = ba[t];

    float wreg[200];
    float btr = 0.0f;
    if (t < 500) {
        const float* wp = Wt + (size_t)t * 200;
#pragma unroll
        for (int k = 0; k < 200; k += 4) {
            const float4 w = *(const float4*)(wp + k);
            wreg[k] = w.x; wreg[k + 1] = w.y; wreg[k + 2] = w.z; wreg[k + 3] = w.w;
        }
        btr = bt[t];
    }

    int sp = 0, bp = 0;
    float encR = 0.0f, encR1 = 0.0f;            // enc[bp], enc[bp+1] (t<200)
    if (t < 200) {
        encR  = g_enc[t];                       // bp = 0
        encR1 = g_enc[200 + t];                 // bp = 1
    }
    __syncthreads();

    for (int k = 0; k < NSTEP; k++) {
        // ---- Phase 1: gather feat = [s1 | s0 | b]; build u = [h1 ; h2] ----
        if (t < 200) {
            const float v1 = (sp >= 2) ? stack[(sp - 2) * 200 + t] : mis_s[t];
            feat[t]       = v1;
            feat[400 + t] = (bp < NSEQ) ? encR : mis_s[t];
            if (t < 100) u_s[t] = v1;                      // h1 = s1[0:100]
        } else if (t < 400) {
            const int j = t - 200;
            const float v0 = (sp >= 1) ? stack[(sp - 1) * 200 + j] : mis_s[j];
            feat[t] = v0;
            if (j < 100) u_s[100 + j] = v0;                // h2 = s0[0:100]
        }
        __syncthreads();

        // ---- Phase 2: decision (warp 0) + speculative matvec (t<500) ----
        if (t < 32) {
            float a0 = 0.0f, a1 = 0.0f;
            for (int k2 = t; k2 < 600; k2 += 32) {
                const float f = feat[k2];
                a0 += wa_s[k2] * f;
                a1 += wa_s[600 + k2] * f;
            }
#pragma unroll
            for (int o = 16; o > 0; o >>= 1) {
                a0 += __shfl_xor_sync(0xffffffffu, a0, o);
                a1 += __shfl_xor_sync(0xffffffffu, a1, o);
            }
            if (t == 0) {
                const float m0 = (bp < NSEQ) ? (a0 + ba_s[0]) : -1e30f;
                const float m1 = (sp >= 2)   ? (a1 + ba_s[1]) : -1e30f;
                dec_s = (m0 >= m1) ? 1 : 0;     // argmax tie -> shift
            }
        }
        if (t < 500) {
            float a0 = 0.f, a1 = 0.f, a2 = 0.f, a3 = 0.f;
#pragma unroll
            for (int k2 = 0; k2 < 200; k2 += 4) {
                const float4 uv = *(const float4*)(u_s + k2);
                a0 += wreg[k2]     * uv.x;
                a1 += wreg[k2 + 1] * uv.y;
                a2 += wreg[k2 + 2] * uv.z;
                a3 += wreg[k2 + 3] * uv.w;
            }
            gat[t] = btr + ((a0 + a1) + (a2 + a3));
        }
        // prefetch enc[bp+2] overlap slot (used only after two shifts)
        __syncthreads();

        // ---- Phase 3: apply ----
        const int dec = dec_s;
        if (dec) {
            int pos = sp; if (pos > NSEQ - 1) pos = NSEQ - 1;
            if (t < 200) stack[pos * 200 + t] = feat[400 + t];
        } else {
            if (t < 100) {
                const float iv = gat[t];
                const float f1 = gat[100 + t];
                const float f2 = gat[200 + t];
                const float ov = gat[300 + t];
                const float uu = gat[400 + t];
                const float c1 = feat[100 + t];   // s1 cell half
                const float c2 = feat[300 + t];   // s0 cell half
                const float c  = sigm(f1) * c1 + sigm(f2) * c2 + sigm(iv) * tanh_f(uu);
                const float h  = sigm(ov) * tanh_f(c);
                int pos = sp - 2; if (pos < 0) pos = 0;
                stack[pos * 200 + t]       = h;
                stack[pos * 200 + 100 + t] = c;
            }
        }
        if (dec) {
            sp += 1; bp += 1;
            if (t < 200) {
                encR  = encR1;
                encR1 = g_enc[(size_t)min(bp + 1, NSEQ - 1) * 200 + t];
            }
        } else {
            sp -= 1;
        }
        __syncthreads();
    }

    if (t < 200) out[t] = stack[t];
}

// ---------------------------------------------------------------------------
// Host launcher
// ---------------------------------------------------------------------------
extern "C" void kernel_launch(void* const* d_in, const int* in_sizes, int n_in,
                              void* d_out, int out_size)
{
    const int*   tokens  = (const int*)  d_in[0];
    const int*   lengths = (const int*)  d_in[1];
    const float* emb     = (const float*)d_in[2];
    const float* Wih_l0  = (const float*)d_in[3];
    const float* Whh_l0  = (const float*)d_in[4];
    const float* b_l0    = (const float*)d_in[5];
    const float* Wih_l12 = (const float*)d_in[6];
    const float* Whh_l12 = (const float*)d_in[7];
    const float* b_l12   = (const float*)d_in[8];
    const float* missing = (const float*)d_in[9];
    const float* Wa      = (const float*)d_in[10];
    const float* ba      = (const float*)d_in[11];
    const float* Wt      = (const float*)d_in[12];
    const float* bt      = (const float*)d_in[13];
    float* out = (float*)d_out;

    const size_t parser_smem = PAR_SMEM_FLOATS * sizeof(float);  // 215,664 B
    cudaFuncSetAttribute(parser_kernel, cudaFuncAttributeMaxDynamicSharedMemorySize,
                         (int)parser_smem);

    const dim3 gg(MTOT / 128, (GNN + 127) / 128);   // (64, 7)

    prof_pad_kernel<<<1, 32>>>();   // shifts ncu -s 5 capture onto sgemm_tn

    sgemm_tn<<<gg, 256>>>(0, Wih_l0, 300, tokens, emb);
    lstm_rec<<<2 * NSEQ, 416>>>(Whh_l0, b_l0, lengths, 0);

    sgemm_tn<<<gg, 256>>>(1, Wih_l12, 200, nullptr, nullptr);
    lstm_rec<<<2 * NSEQ, 416>>>(Whh_l12, b_l12, lengths, 1);

    sgemm_tn<<<gg, 256>>>(2, Wih_l12 + 2 * 400 * 200, 200, nullptr, nullptr);
    lstm_rec<<<2 * NSEQ, 416>>>(Whh_l12 + 2 * 400 * 100, b_l12 + 800, lengths, 0);

    enc_kernel<<<NSEQ, 256>>>(lengths);

    parser_kernel<<<1, 512, parser_smem>>>(missing, Wa, ba, Wt, bt, out);
}